// round 16
// baseline (speedup 1.0000x reference)
#include <cuda_runtime.h>
#include <cuda_fp16.h>
#include <cstdint>

#define S_LEN   2048
#define DMODEL  2048
#define DKV     512
#define NH      32
#define NKV     8
#define HD      64

// ---------------- scratch (static device globals; no allocation) ----------------
__device__ __align__(16) int8_t g_q8[S_LEN * DMODEL];   // 4 MB
__device__ __align__(16) int8_t g_k8[S_LEN * DKV];      // 1 MB
__device__ __align__(16) float  g_qsi[NH  * S_LEN];     // 0.125/scale, [head][token]
__device__ __align__(16) float  g_ksi[NKV * S_LEN];     // 1/scale,     [kvh][token]
__device__ __align__(16) __half g_vh[S_LEN * DKV];      // V in fp16

// hybrid operands for the QKV projection
__device__ __align__(16) __half g_xh[S_LEN * DMODEL];   // fp16(x)
__device__ __align__(16) int8_t g_x1[S_LEN * DMODEL];   // int8(x)        / s1x
__device__ __align__(16) int8_t g_x2[S_LEN * DMODEL];   // int8(x-fp16x)  / s2x
__device__ float g_sx1[S_LEN], g_sx2[S_LEN];
__device__ __align__(16) __half g_wh[3072 * DMODEL];
__device__ __align__(16) int8_t g_w1[3072 * DMODEL];
__device__ __align__(16) int8_t g_w2[3072 * DMODEL];
__device__ float g_sw1[3072], g_sw2[3072];

__device__ __align__(16) __half g_woh[DMODEL * DMODEL];
__device__ __align__(16) __half g_ah[S_LEN * DMODEL];

#define NEG_INF (__int_as_float(0xff800000))

// =====================================================================
// helpers
// =====================================================================
__device__ __forceinline__ void mma_f16(float* c, const uint32_t* a,
                                        uint32_t b0, uint32_t b1) {
    asm("mma.sync.aligned.m16n8k16.row.col.f32.f16.f16.f32 "
        "{%0,%1,%2,%3}, {%4,%5,%6,%7}, {%8,%9}, {%0,%1,%2,%3};"
        : "+f"(c[0]), "+f"(c[1]), "+f"(c[2]), "+f"(c[3])
        : "r"(a[0]), "r"(a[1]), "r"(a[2]), "r"(a[3]), "r"(b0), "r"(b1));
}

__device__ __forceinline__ void mma_f16s(float* c, uint32_t a0, uint32_t a1,
                                         uint32_t a2, uint32_t a3,
                                         uint32_t b0, uint32_t b1) {
    asm("mma.sync.aligned.m16n8k16.row.col.f32.f16.f16.f32 "
        "{%0,%1,%2,%3}, {%4,%5,%6,%7}, {%8,%9}, {%0,%1,%2,%3};"
        : "+f"(c[0]), "+f"(c[1]), "+f"(c[2]), "+f"(c[3])
        : "r"(a0), "r"(a1), "r"(a2), "r"(a3), "r"(b0), "r"(b1));
}

__device__ __forceinline__ void mma_s8(int* c, const uint32_t* a,
                                       uint32_t b0, uint32_t b1) {
    asm("mma.sync.aligned.m16n8k32.row.col.s32.s8.s8.s32 "
        "{%0,%1,%2,%3}, {%4,%5,%6,%7}, {%8,%9}, {%0,%1,%2,%3};"
        : "+r"(c[0]), "+r"(c[1]), "+r"(c[2]), "+r"(c[3])
        : "r"(a[0]), "r"(a[1]), "r"(a[2]), "r"(a[3]), "r"(b0), "r"(b1));
}

__device__ __forceinline__ void mma_s8v(int* c, const int* a, int b0, int b1) {
    asm("mma.sync.aligned.m16n8k32.row.col.s32.s8.s8.s32 "
        "{%0,%1,%2,%3}, {%4,%5,%6,%7}, {%8,%9}, {%0,%1,%2,%3};"
        : "+r"(c[0]), "+r"(c[1]), "+r"(c[2]), "+r"(c[3])
        : "r"(a[0]), "r"(a[1]), "r"(a[2]), "r"(a[3]), "r"(b0), "r"(b1));
}

#define LDSM4(r, a) \
    asm volatile("ldmatrix.sync.aligned.m8n8.x4.shared.b16 {%0,%1,%2,%3}, [%4];" \
                 : "=r"((r)[0]), "=r"((r)[1]), "=r"((r)[2]), "=r"((r)[3]) : "r"(a))

#define LDSM2T(r0, r1, a) \
    asm volatile("ldmatrix.sync.aligned.m8n8.x2.trans.shared.b16 {%0,%1}, [%2];" \
                 : "=r"(r0), "=r"(r1) : "r"(a))

#define CP_ASYNC16(dst, src) \
    asm volatile("cp.async.ca.shared.global [%0], [%1], 16;" :: "r"(dst), "l"(src))
#define CP_COMMIT() asm volatile("cp.async.commit_group;")
#define CP_WAIT(n)  asm volatile("cp.async.wait_group %0;" :: "n"(n))

__device__ __forceinline__ uint32_t smem_u32(const void* p) {
    uint32_t a;
    asm("{ .reg .u64 t; cvta.to.shared.u64 t, %1; cvt.u32.u64 %0, t; }" : "=r"(a) : "l"(p));
    return a;
}

// =====================================================================
// Prep: per-row hybrid operands. Blocks: 0..2047 x rows, 2048..5119 W rows,
// 5120..7167 Wo rows (fp16 only).
// =====================================================================
__global__ __launch_bounds__(256) void prep_kernel(
    const float* __restrict__ x, const float* __restrict__ Wq,
    const float* __restrict__ Wk, const float* __restrict__ Wv,
    const float* __restrict__ Wo)
{
    const int b   = blockIdx.x;
    const int tid = threadIdx.x;

    if (b >= 5120) {                       // Wo rows -> fp16
        const int r = b - 5120;
        const float* src = Wo + (size_t)r * DMODEL;
        __half* dst = g_woh + (size_t)r * DMODEL;
#pragma unroll
        for (int i = 0; i < 2; i++) {
            float4 v = reinterpret_cast<const float4*>(src)[tid * 2 + i];
            *reinterpret_cast<__half2*>(dst + tid * 8 + i * 4)     = __floats2half2_rn(v.x, v.y);
            *reinterpret_cast<__half2*>(dst + tid * 8 + i * 4 + 2) = __floats2half2_rn(v.z, v.w);
        }
        return;
    }

    const float* src;
    __half* dh; int8_t *d1, *d2;
    float *s1dst, *s2dst;
    if (b < 2048) {
        src = x + (size_t)b * DMODEL;
        dh = g_xh + (size_t)b * DMODEL;
        d1 = g_x1 + (size_t)b * DMODEL; d2 = g_x2 + (size_t)b * DMODEL;
        s1dst = &g_sx1[b]; s2dst = &g_sx2[b];
    } else {
        int r = b - 2048;
        src = (r < 2048) ? Wq + (size_t)r * DMODEL
            : (r < 2560) ? Wk + (size_t)(r - 2048) * DMODEL
                         : Wv + (size_t)(r - 2560) * DMODEL;
        dh = g_wh + (size_t)r * DMODEL;
        d1 = g_w1 + (size_t)r * DMODEL; d2 = g_w2 + (size_t)r * DMODEL;
        s1dst = &g_sw1[r]; s2dst = &g_sw2[r];
    }

    float4 v0 = reinterpret_cast<const float4*>(src)[tid * 2];
    float4 v1 = reinterpret_cast<const float4*>(src)[tid * 2 + 1];
    float vals[8] = {v0.x, v0.y, v0.z, v0.w, v1.x, v1.y, v1.z, v1.w};

    __half hv[8];
    float  lo[8];
    float amv = 0.f, aml = 0.f;
#pragma unroll
    for (int i = 0; i < 8; i++) {
        hv[i] = __float2half_rn(vals[i]);
        lo[i] = vals[i] - __half2float(hv[i]);
        amv = fmaxf(amv, fabsf(vals[i]));
        aml = fmaxf(aml, fabsf(lo[i]));
    }
#pragma unroll
    for (int off = 16; off; off >>= 1) {
        amv = fmaxf(amv, __shfl_xor_sync(0xffffffffu, amv, off));
        aml = fmaxf(aml, __shfl_xor_sync(0xffffffffu, aml, off));
    }
    __shared__ float wv[8], wl[8];
    if ((tid & 31) == 0) { wv[tid >> 5] = amv; wl[tid >> 5] = aml; }
    __syncthreads();
    float av = 1e-30f, al = 1e-30f;
#pragma unroll
    for (int i = 0; i < 8; i++) { av = fmaxf(av, wv[i]); al = fmaxf(al, wl[i]); }
    const float s1 = av * (1.f / 127.f), i1 = 127.f / av;
    const float s2 = al * (1.f / 127.f), i2 = 127.f / al;

    // store fp16 hi
#pragma unroll
    for (int i = 0; i < 2; i++) {
        __half2 p0; p0.x = hv[i * 4];     p0.y = hv[i * 4 + 1];
        __half2 p1; p1.x = hv[i * 4 + 2]; p1.y = hv[i * 4 + 3];
        *reinterpret_cast<__half2*>(dh + tid * 8 + i * 4)     = p0;
        *reinterpret_cast<__half2*>(dh + tid * 8 + i * 4 + 2) = p1;
    }
    // store int8 levels
    uint32_t p1w[2] = {0, 0}, p2w[2] = {0, 0};
#pragma unroll
    for (int i = 0; i < 8; i++) {
        int q1 = min(127, max(-127, __float2int_rn(vals[i] * i1)));
        int q2 = min(127, max(-127, __float2int_rn(lo[i]   * i2)));
        p1w[i >> 2] |= (uint32_t)(q1 & 255) << ((i & 3) * 8);
        p2w[i >> 2] |= (uint32_t)(q2 & 255) << ((i & 3) * 8);
    }
    *reinterpret_cast<uint2*>(d1 + tid * 8) = make_uint2(p1w[0], p1w[1]);
    *reinterpret_cast<uint2*>(d2 + tid * 8) = make_uint2(p2w[0], p2w[1]);
    if (tid == 0) { *s1dst = s1; *s2dst = s2; }
}

// =====================================================================
// QKV GEMM (hybrid): C = Ah*Bh (fp16) + a1q*b2q*s1x*s2w + a2q*b1q*s2x*s1w
//   Q/K: all 3 parts; V: Ah*Bh + a2q*b1q only.
// CTA 128x128, 8 warps 32x64, BK=32, 4-stage cp.async, 1 CTA/SM.
// =====================================================================
#define AH_OFF   0          // 128 x 80B (64B data)
#define A1_OFF   10240      // 128 x 48B (32B data)
#define A2_OFF   16384
#define BH_OFF   22528
#define B1_OFF   32768
#define B2_OFF   38912
#define QSTAGE_B 45056
#define QSMEM    (4 * QSTAGE_B)   // 180224
#define QKITER   64               // 2048 / 32

__global__ __launch_bounds__(256, 1) void qkv_gemm()
{
    extern __shared__ char smem[];
    __shared__ float sx1t[128], sx2t[128], sw1t[128], sw2t[128];
    const uint32_t sbase = smem_u32(smem);
    const int tid  = threadIdx.x;
    const int wid  = tid >> 5;
    const int lane = tid & 31;
    const int m0   = blockIdx.x * 128;
    const int n0   = blockIdx.y * 128;     // V tiles (y>=20) launch last
    const int wm   = (wid & 3) * 32;
    const int wn   = (wid >> 2) * 64;

    const int  mode = (n0 < 2048) ? 0 : (n0 < 2560) ? 1 : 2;   // 0=Q 1=K 2=V
    const bool qk   = (mode <= 1);

    const __half* srcAh = g_xh + (size_t)m0 * DMODEL;
    const int8_t* srcA1 = g_x1 + (size_t)m0 * DMODEL;
    const int8_t* srcA2 = g_x2 + (size_t)m0 * DMODEL;
    const __half* srcBh = g_wh + (size_t)n0 * DMODEL;
    const int8_t* srcB1 = g_w1 + (size_t)n0 * DMODEL;
    const int8_t* srcB2 = g_w2 + (size_t)n0 * DMODEL;

    if (tid < 128) {
        sx1t[tid] = g_sx1[m0 + tid]; sx2t[tid] = g_sx2[m0 + tid];
        sw1t[tid] = g_sw1[n0 + tid]; sw2t[tid] = g_sw2[n0 + tid];
    }

    // fragment address bases (within a stage)
    const uint32_t aAddrH = sbase + AH_OFF + (wm + (lane & 15)) * 80 + ((lane >> 4) << 4);
    const uint32_t bAddrH = sbase + BH_OFF +
        (wn + (lane & 7) + ((lane >> 4) & 1) * 8) * 80 + (((lane >> 3) & 1) << 4);
    const uint32_t aAddr1 = sbase + A1_OFF + (wm + (lane & 15)) * 48 + ((lane >> 4) << 4);
    const uint32_t aAddr2 = sbase + A2_OFF + (wm + (lane & 15)) * 48 + ((lane >> 4) << 4);
    const uint32_t bAddr1 = sbase + B1_OFF +
        (wn + (lane & 7) + ((lane >> 4) & 1) * 8) * 48 + (((lane >> 3) & 1) << 4);
    const uint32_t bAddr2 = sbase + B2_OFF +
        (wn + (lane & 7) + ((lane >> 4) & 1) * 8) * 48 + (((lane >> 3) & 1) << 4);

    float accF[2][8][4];
    int   acc1[2][8][4], acc2[2][8][4];
#pragma unroll
    for (int mt = 0; mt < 2; mt++)
#pragma unroll
        for (int nt = 0; nt < 8; nt++)
#pragma unroll
            for (int i = 0; i < 4; i++) {
                accF[mt][nt][i] = 0.f; acc1[mt][nt][i] = 0; acc2[mt][nt][i] = 0;
            }

    const int r0 = tid >> 1;
    const int h0 = tid & 1;

    auto load_stage = [&](int it) {
        const int kc = it * 32;                       // element offset in K
        const uint32_t db = sbase + (it & 3) * QSTAGE_B;
        // Ah/Bh: 2 chunks each (16B = 8 fp16)
#pragma unroll
        for (int i = 0; i < 2; i++) {
            const int seg = h0 * 2 + i;               // 0..3
            CP_ASYNC16(db + AH_OFF + r0 * 80 + seg * 16,
                       (const char*)(srcAh + (size_t)r0 * DMODEL + kc) + seg * 16);
            CP_ASYNC16(db + BH_OFF + r0 * 80 + seg * 16,
                       (const char*)(srcBh + (size_t)r0 * DMODEL + kc) + seg * 16);
        }
        // a2/b1: 1 chunk each (16B = 16 int8)
        CP_ASYNC16(db + A2_OFF + r0 * 48 + h0 * 16,
                   (const char*)(srcA2 + (size_t)r0 * DMODEL + kc) + h0 * 16);
        CP_ASYNC16(db + B1_OFF + r0 * 48 + h0 * 16,
                   (const char*)(srcB1 + (size_t)r0 * DMODEL + kc) + h0 * 16);
        if (qk) {
            CP_ASYNC16(db + A1_OFF + r0 * 48 + h0 * 16,
                       (const char*)(srcA1 + (size_t)r0 * DMODEL + kc) + h0 * 16);
            CP_ASYNC16(db + B2_OFF + r0 * 48 + h0 * 16,
                       (const char*)(srcB2 + (size_t)r0 * DMODEL + kc) + h0 * 16);
        }
    };

    load_stage(0); CP_COMMIT();
    load_stage(1); CP_COMMIT();
    load_stage(2); CP_COMMIT();

    for (int it = 0; it < QKITER; it++) {
        CP_WAIT(2);
        __syncthreads();
        if (it + 3 < QKITER) load_stage(it + 3);
        CP_COMMIT();

        const uint32_t off = (it & 3) * QSTAGE_B;

        // ---- fp16 part: Ah*Bh over 2 k16 steps ----
#pragma unroll
        for (int s = 0; s < 2; s++) {
            uint32_t ah[2][4], bh[4][4];
#pragma unroll
            for (int mt = 0; mt < 2; mt++)
                LDSM4(ah[mt], aAddrH + off + mt * (16 * 80) + s * 32);
#pragma unroll
            for (int np = 0; np < 4; np++)
                LDSM4(bh[np], bAddrH + off + np * (16 * 80) + s * 32);
#pragma unroll
            for (int mt = 0; mt < 2; mt++)
#pragma unroll
                for (int nt = 0; nt < 8; nt++)
                    mma_f16(accF[mt][nt], ah[mt],
                            bh[nt >> 1][(nt & 1) * 2], bh[nt >> 1][(nt & 1) * 2 + 1]);
        }

        // ---- s8 cross 2: a2q * b1q ----
        {
            uint32_t af[2][4], bf[4][4];
#pragma unroll
            for (int mt = 0; mt < 2; mt++)
                LDSM4(af[mt], aAddr2 + off + mt * (16 * 48));
#pragma unroll
            for (int np = 0; np < 4; np++)
                LDSM4(bf[np], bAddr1 + off + np * (16 * 48));
#pragma unroll
            for (int mt = 0; mt < 2; mt++)
#pragma unroll
                for (int nt = 0; nt < 8; nt++)
                    mma_s8(acc2[mt][nt], af[mt],
                           bf[nt >> 1][(nt & 1) * 2], bf[nt >> 1][(nt & 1) * 2 + 1]);
        }
        // ---- s8 cross 1 (Q/K only): a1q * b2q ----
        if (qk) {
            uint32_t af[2][4], bf[4][4];
#pragma unroll
            for (int mt = 0; mt < 2; mt++)
                LDSM4(af[mt], aAddr1 + off + mt * (16 * 48));
#pragma unroll
            for (int np = 0; np < 4; np++)
                LDSM4(bf[np], bAddr2 + off + np * (16 * 48));
#pragma unroll
            for (int mt = 0; mt < 2; mt++)
#pragma unroll
                for (int nt = 0; nt < 8; nt++)
                    mma_s8(acc1[mt][nt], af[mt],
                           bf[nt >> 1][(nt & 1) * 2], bf[nt >> 1][(nt & 1) * 2 + 1]);
        }
    }

    // ---- epilogue: combine + quant (Q/K) or fp16 store (V) ----
    const int qrow = lane >> 2;
    const int qcol = (lane & 3) * 2;
#pragma unroll
    for (int mt = 0; mt < 2; mt++) {
#pragma unroll
        for (int h = 0; h < 2; h++) {
            const int rl  = wm + mt * 16 + qrow + h * 8;
            const int row = m0 + rl;
            const float s1x = sx1t[rl], s2x = sx2t[rl];
            float vv[8][2];
#pragma unroll
            for (int nt = 0; nt < 8; nt++) {
                const int cl = wn + nt * 8 + qcol;
                float v0 = accF[mt][nt][h * 2]     + (float)acc2[mt][nt][h * 2]     * s2x * sw1t[cl];
                float v1 = accF[mt][nt][h * 2 + 1] + (float)acc2[mt][nt][h * 2 + 1] * s2x * sw1t[cl + 1];
                if (qk) {
                    v0 += (float)acc1[mt][nt][h * 2]     * s1x * sw2t[cl];
                    v1 += (float)acc1[mt][nt][h * 2 + 1] * s1x * sw2t[cl + 1];
                }
                vv[nt][0] = v0; vv[nt][1] = v1;
            }
            if (qk) {
                float am = 0.f;
#pragma unroll
                for (int nt = 0; nt < 8; nt++)
                    am = fmaxf(am, fmaxf(fabsf(vv[nt][0]), fabsf(vv[nt][1])));
                am = fmaxf(am, __shfl_xor_sync(0xffffffffu, am, 1));
                am = fmaxf(am, __shfl_xor_sync(0xffffffffu, am, 2));
                float scale = 127.f / fmaxf(am, 1e-6f);
#pragma unroll
                for (int nt = 0; nt < 8; nt++) {
                    int v0 = min(127, max(-127, __float2int_rn(vv[nt][0] * scale)));
                    int v1 = min(127, max(-127, __float2int_rn(vv[nt][1] * scale)));
                    unsigned short pk = (unsigned short)((v0 & 255) | ((v1 & 255) << 8));
                    if (mode == 0)
                        *reinterpret_cast<unsigned short*>(
                            &g_q8[(size_t)row * DMODEL + n0 + wn + nt * 8 + qcol]) = pk;
                    else
                        *reinterpret_cast<unsigned short*>(
                            &g_k8[(size_t)row * DKV + (n0 - 2048) + wn + nt * 8 + qcol]) = pk;
                }
                if ((lane & 3) == 0) {
                    if (mode == 0)
                        g_qsi[(size_t)((n0 + wn) >> 6) * S_LEN + row] = 0.125f / scale;
                    else
                        g_ksi[(size_t)(((n0 - 2048) + wn) >> 6) * S_LEN + row] = 1.f / scale;
                }
            } else {
#pragma unroll
                for (int nt = 0; nt < 8; nt++) {
                    __half2 hv = __floats2half2_rn(vv[nt][0], vv[nt][1]);
                    *reinterpret_cast<__half2*>(
                        &g_vh[(size_t)row * DKV + (n0 - 2560) + wn + nt * 8 + qcol]) = hv;
                }
            }
        }
    }
}

// =====================================================================
// Out GEMM: 1-term fp16, CTA 128x256 (8 warps of 64x64), single wave.
// =====================================================================
#define GP        48
#define NSTAGE    4
#define WA_TILE   6144
#define WSTAGE_B  18432
#define WSMEM_DYN (NSTAGE * WSTAGE_B)
#define KITER     128

__global__ __launch_bounds__(256, 1) void out_gemm(float* __restrict__ outp)
{
    extern __shared__ char smem[];
    const uint32_t sbase = smem_u32(smem);
    const int tid  = threadIdx.x;
    const int wid  = tid >> 5;
    const int lane = tid & 31;
    const int m0   = blockIdx.x * 128;
    const int n0   = blockIdx.y * 256;
    const int wm   = (wid & 1) * 64;
    const int wn   = (wid >> 1) * 64;

    const __half* Asrc = g_ah  + (size_t)m0 * DMODEL;
    const __half* Bsrc = g_woh + (size_t)n0 * DMODEL;

    const int r0 = tid >> 1;
    const int sb = (tid & 1) * 16;
    const size_t go = (size_t)r0 * DMODEL + (tid & 1) * 8;

    const uint32_t aAddr = sbase + (wm + (lane & 15)) * GP + ((lane >> 4) << 4);
    const uint32_t bAddr = sbase + WA_TILE +
        (wn + (lane & 7) + ((lane >> 4) & 1) * 8) * GP + (((lane >> 3) & 1) << 4);

    float acc[4][8][4];
#pragma unroll
    for (int mt = 0; mt < 4; mt++)
#pragma unroll
        for (int nt = 0; nt < 8; nt++)
#pragma unroll
            for (int i = 0; i < 4; i++) acc[mt][nt][i] = 0.f;

    auto load_stage = [&](int it) {
        const int kc = it * 16;
        const uint32_t db = sbase + (it & (NSTAGE - 1)) * WSTAGE_B + r0 * GP + sb;
        CP_ASYNC16(db,                       (const char*)(Asrc + go + kc));
        CP_ASYNC16(db + WA_TILE,             (const char*)(Bsrc + go + kc));
        CP_ASYNC16(db + WA_TILE + 128 * GP,
                   (const char*)(Bsrc + go + (size_t)128 * DMODEL + kc));
    };

    load_stage(0); CP_COMMIT();
    load_stage(1); CP_COMMIT();
    load_stage(2); CP_COMMIT();

    for (int it = 0; it < KITER; it++) {
        CP_WAIT(2);
        __syncthreads();
        if (it + 3 < KITER) load_stage(it + 3);
        CP_COMMIT();

        const uint32_t off = (it & (NSTAGE - 1)) * WSTAGE_B;
        const uint32_t ab = aAddr + off;
        const uint32_t bb = bAddr + off;
        uint32_t ah[4][4], bh[4][4];
#pragma unroll
        for (int q = 0; q < 4; q++)
            LDSM4(ah[q], ab + q * (16 * GP));
#pragma unroll
        for (int np = 0; np < 4; np++)
            LDSM4(bh[np], bb + np * (16 * GP));
#pragma unroll
        for (int mt = 0; mt < 4; mt++)
#pragma unroll
            for (int nt = 0; nt < 8; nt++)
                mma_f16(acc[mt][nt], ah[mt],
                        bh[nt >> 1][(nt & 1) * 2], bh[nt >> 1][(nt & 1) * 2 + 1]);
    }

    const int qrow = lane >> 2;
    const int qcol = (lane & 3) * 2;
#pragma unroll
    for (int mt = 0; mt < 4; mt++)
#pragma unroll
        for (int h = 0; h < 2; h++) {
            const int row = m0 + wm + mt * 16 + qrow + h * 8;
#pragma unroll
            for (int nt = 0; nt < 8; nt++) {
                float2 v = make_float2(acc[mt][nt][h * 2], acc[mt][nt][h * 2 + 1]);
                *reinterpret_cast<float2*>(
                    &outp[(size_t)row * DMODEL + n0 + wn + nt * 8 + qcol]) = v;
            }
        }
}

// =====================================================================
// Attention: s8 scores + fp16 PV; K/V/scales double-buffered via cp.async
// =====================================================================
__global__ __launch_bounds__(128) void attn_kernel()
{
    const int h    = blockIdx.y;
    const int qb   = gridDim.x - 1 - blockIdx.x;
    const int kvh  = h >> 2;
    const int tid  = threadIdx.x;
    const int warp = tid >> 5;
    const int lane = tid & 31;
    const int g    = lane >> 2;
    const int tg   = lane & 3;
    const int rbase = warp * 16;

    __shared__ __align__(16) int    qsm[64][20];
    __shared__ __align__(16) int    ksm[2][64][20];
    __shared__ __align__(16) __half vsm[2][64][72];
    __shared__ __align__(16) __half psm[64][72];
    __shared__ __align__(16) float  kinvs[2][64];
    __shared__ float qfac[64];

    const uint32_t ks_base = smem_u32(&ksm[0][0][0]);
    const uint32_t vs_base = smem_u32(&vsm[0][0][0]);
    const uint32_t ki_base = smem_u32(&kinvs[0][0]);

#pragma unroll
    for (int i = 0; i < 2; i++) {
        int idx = tid + i * 128;
        int row = idx >> 2;
        int seg = idx & 3;
        int4 v = *reinterpret_cast<const int4*>(
            &g_q8[(size_t)(qb * 64 + row) * DMODEL + h * 64 + seg * 16]);
        *reinterpret_cast<int4*>(&qsm[row][seg * 4]) = v;
    }
    if (tid < 64) qfac[tid] = g_qsi[(size_t)h * S_LEN + qb * 64 + tid];

    auto load_kv = [&](int j, int buf) {
        const uint32_t kb = ks_base + buf * 5120;
#pragma unroll
        for (int i = 0; i < 2; i++) {
            int idx = tid + i * 128;
            int row = idx >> 2, seg = idx & 3;
            CP_ASYNC16(kb + row * 80 + seg * 16,
                       (const char*)(g_k8 + (size_t)(j * 64 + row) * DKV + kvh * 64) + seg * 16);
        }
        const uint32_t vb = vs_base + buf * 9216;
#pragma unroll
        for (int i = 0; i < 4; i++) {
            int idx = tid + i * 128;
            int row = idx >> 3, seg = idx & 7;
            CP_ASYNC16(vb + row * 144 + seg * 16,
                       (const char*)(g_vh + (size_t)(j * 64 + row) * DKV + kvh * 64) + seg * 16);
        }
        if (tid < 16)
            CP_ASYNC16(ki_base + buf * 256 + tid * 16,
                       (const char*)(g_ksi + (size_t)kvh * S_LEN + j * 64) + tid * 16);
    };

    int qa[2][4];
    __syncthreads();
#pragma unroll
    for (int s = 0; s < 2; s++) {
        qa[s][0] = qsm[rbase + g    ][s * 8 + tg];
        qa[s][1] = qsm[rbase + g + 8][s * 8 + tg];
        qa[s][2] = qsm[rbase + g    ][s * 8 + 4 + tg];
        qa[s][3] = qsm[rbase + g + 8][s * 8 + 4 + tg];
    }

    const int   rowA = rbase + g, rowB = rowA + 8;
    const float qfA  = qfac[rowA], qfB = qfac[rowB];
    const int   qgA  = qb * 64 + rowA, qgB = qb * 64 + rowB;

    float acc[8][4];
#pragma unroll
    for (int nt = 0; nt < 8; nt++)
#pragma unroll
        for (int i = 0; i < 4; i++) acc[nt][i] = 0.f;
    float m_runA = NEG_INF, m_runB = NEG_INF;
    float l_runA = 0.f,     l_runB = 0.f;

    load_kv(0, 0); CP_COMMIT();

    for (int j = 0; j <= qb; j++) {
        const int buf = j & 1;
        if (j < qb) load_kv(j + 1, buf ^ 1);
        CP_COMMIT();
        CP_WAIT(1);
        __syncthreads();

        const uint32_t vbase = vs_base + buf * 9216 + (lane & 15) * 144;

        int sc[8][4];
#pragma unroll
        for (int nt = 0; nt < 8; nt++) {
            sc[nt][0] = sc[nt][1] = sc[nt][2] = sc[nt][3] = 0;
#pragma unroll
            for (int s = 0; s < 2; s++) {
                int b0 = ksm[buf][nt * 8 + g][s * 8 + tg];
                int b1 = ksm[buf][nt * 8 + g][s * 8 + 4 + tg];
                int av[4] = {qa[s][0], qa[s][1], qa[s][2], qa[s][3]};
                mma_s8v(sc[nt], av, b0, b1);
            }
        }

        const bool maskblk = (j == qb);
        float sv[8][4];
        float mxA = NEG_INF, mxB = NEG_INF;
#pragma unroll
        for (int nt = 0; nt < 8; nt++) {
            int colbase = nt * 8 + tg * 2;
            float2 kv = *reinterpret_cast<const float2*>(&kinvs[buf][colbase]);
            float s0 = (float)sc[nt][0] * qfA * kv.x;
            float s1 = (float)sc[nt][1] * qfA * kv.y;
            float s2 = (float)sc[nt][2] * qfB * kv.x;
            float s3 = (float)sc[nt][3] * qfB * kv.y;
            if (maskblk) {
                int col = j * 64 + colbase;
                if (col     > qgA) s0 = NEG_INF;
                if (col + 1 > qgA) s1 = NEG_INF;
                if (col     > qgB) s2 = NEG_INF;
                if (col + 1 > qgB) s3 = NEG_INF;
            }
            sv[nt][0] = s0; sv[nt][1] = s1; sv[nt][2] = s2; sv[nt][3] = s3;
            mxA = fmaxf(mxA, fmaxf(s0, s1));
            mxB = fmaxf(mxB, fmaxf(s2, s3));
        }
        mxA = fmaxf(mxA, __shfl_xor_sync(0xffffffffu, mxA, 1));
        mxA = fmaxf(mxA, __shfl_xor_sync(0xffffffffu, mxA, 2));
        mxB = fmaxf(mxB, __shfl_xor_sync(0xffffffffu, mxB, 1));
        mxB = fmaxf(mxB, __shfl_xor_sync(0xffffffffu, mxB, 2));

        float mA = fmaxf(m_runA, mxA);
        float mB = fmaxf(m_runB, mxB);
        float aA = __expf(m_runA - mA);
        float aB = __expf(m_runB - mB);
        m_runA = mA; m_runB = mB;

        float sumA = 0.f, sumB = 0.f;
#pragma unroll
        for (int nt = 0; nt < 8; nt++) {
            int colbase = nt * 8 + tg * 2;
            float p0 = __expf(sv[nt][0] - mA);
            float p1 = __expf(sv[nt][1] - mA);
            float p2 = __expf(sv[nt][2] - mB);
            float p3 = __expf(sv[nt][3] - mB);
            sumA += p0 + p1; sumB += p2 + p3;
            *reinterpret_cast<__half2*>(&psm[rowA][colbase]) = __floats2half2_rn(p0, p1);
            *reinterpret_cast<__half2*>(&psm[rowB][colbase]) = __floats2half2_rn(p2, p3);
        }
        sumA += __shfl_xor_sync(0xffffffffu, sumA, 1);
        sumA += __shfl_xor_sync(0xffffffffu, sumA, 2);
        sumB += __shfl_xor_sync(0xffffffffu, sumB, 1);
        sumB += __shfl_xor_sync(0xffffffffu, sumB, 2);
        l_runA = l_runA * aA + sumA;
        l_runB = l_runB * aB + sumB;

#pragma unroll
        for (int nt = 0; nt < 8; nt++) {
            acc[nt][0] *= aA; acc[nt][1] *= aA;
            acc[nt][2] *= aB; acc[nt][3] *= aB;
        }

        __syncwarp();

#pragma unroll
        for (int ks = 0; ks < 4; ks++) {
            uint32_t a0 = *reinterpret_cast<const uint32_t*>(&psm[rowA][ks * 16 + tg * 2]);
            uint32_t a1 = *reinterpret_cast<const uint32_t*>(&psm[rowB][ks * 16 + tg * 2]);
            uint32_t a2 = *reinterpret_cast<const uint32_t*>(&psm[rowA][ks * 16 + 8 + tg * 2]);
            uint32_t a3 = *reinterpret_cast<const uint32_t*>(&psm[rowB][ks * 16 + 8 + tg * 2]);
            const uint32_t vrow = vbase + ks * (16 * 144);
#pragma unroll
            for (int nt = 0; nt < 8; nt++) {
                uint32_t b0, b1;
                LDSM2T(b0, b1, vrow + nt * 16);
                mma_f16s(acc[nt], a0, a1, a2, a3, b0, b1);
            }
        }

        __syncthreads();
    }

    float ilA = 1.f / l_runA, ilB = 1.f / l_runB;
#pragma unroll
    for (int nt = 0; nt < 8; nt++) {
        int colbase = nt * 8 + tg * 2;
        float oA0 = acc[nt][0] * ilA, oA1 = acc[nt][1] * ilA;
        float oB0 = acc[nt][2] * ilB, oB1 = acc[nt][3] * ilB;
        size_t pA = (size_t)qgA * DMODEL + h * 64 + colbase;
        size_t pB = (size_t)qgB * DMODEL + h * 64 + colbase;
        *reinterpret_cast<__half2*>(&g_ah[pA]) = __floats2half2_rn(oA0, oA1);
        *reinterpret_cast<__half2*>(&g_ah[pB]) = __floats2half2_rn(oB0, oB1);
    }
}

// =====================================================================
extern "C" void kernel_launch(void* const* d_in, const int* in_sizes, int n_in,
                              void* d_out, int out_size)
{
    const float* x  = (const float*)d_in[0];
    const float* Wq = (const float*)d_in[1];
    const float* Wk = (const float*)d_in[2];
    const float* Wv = (const float*)d_in[3];
    const float* Wo = (const float*)d_in[4];
    float* out = (float*)d_out;

    cudaFuncSetAttribute(qkv_gemm, cudaFuncAttributeMaxDynamicSharedMemorySize, QSMEM);
    cudaFuncSetAttribute(out_gemm, cudaFuncAttributeMaxDynamicSharedMemorySize, WSMEM_DYN);

    prep_kernel<<<7168, 256>>>(x, Wq, Wk, Wv, Wo);
    qkv_gemm<<<dim3(16, 24), 256, QSMEM>>>();               // hybrid fp16+s8 QKV
    attn_kernel<<<dim3(32, 32), 128>>>();
    out_gemm<<<dim3(16, 8), 256, WSMEM_DYN>>>(out);
}